// round 4
// baseline (speedup 1.0000x reference)
#include <cuda_runtime.h>
#include <cstddef>

// Problem constants
#define OBS_LEN 8
#define FUT_LEN 12
#define NCOORD  2
#define SD      448   // S_DIM + Z_DIM
#define HDIM    512   // SD + NOISE
#define KSAMP   20
#define NPED    2048
#define MROWS   32    // rows per block
#define NTHREADS 256

#define FBUF 16384                 // 512*32 floats per state buffer
#define SMEM_FLOATS (3*FBUF + 64)  // hhA, hhB, cc, s_in
#define SMEM_BYTES  (SMEM_FLOATS * 4)

__device__ __forceinline__ float hsig(float x) {
    return fminf(fmaxf(x * (1.0f / 6.0f) + 0.5f, 0.0f), 1.0f);
}
__device__ __forceinline__ float htanh(float x) {
    return fminf(fmaxf(x, -1.0f), 1.0f);
}
__device__ __forceinline__ float lrelu(float x) {
    return fmaxf(x, 0.01f * x);
}
__device__ __forceinline__ float dot4acc(float4 w, float4 x, float a) {
    a = fmaf(w.x, x.x, a);
    a = fmaf(w.y, x.y, a);
    a = fmaf(w.z, x.z, a);
    a = fmaf(w.w, x.w, a);
    return a;
}

// State layout LL(j, r): float4 array F[(j>>2)*32 + r], component (j&3).
// - GEMM k-reads:   F[k4*32 + lane]          (LDS.128, 4-phase, conflict-free)
// - per-cell write: F[(j0>>2)*32 + lane]     (chunk j0 aligned to 4)

__global__ void __launch_bounds__(NTHREADS, 1)
predictor_kernel(const float* __restrict__ obs,    // (8,2048,2)
                 const float* __restrict__ plh,    // (20,2048,448)
                 const float* __restrict__ zdec,   // (64,64)
                 const float* __restrict__ W1,     // (512,448)
                 const float* __restrict__ b1,     // (512)
                 const float* __restrict__ W2,     // (448,512)
                 const float* __restrict__ b2,     // (448)
                 const float* __restrict__ Wih,    // (2048,2)
                 const float* __restrict__ Whh,    // (2048,512)
                 const float* __restrict__ bih,    // (2048)
                 const float* __restrict__ bhh,    // (2048)
                 const float* __restrict__ Wpos,   // (2,512)
                 const float* __restrict__ bpos,   // (2)
                 float* __restrict__ out)          // (12,20,2048,2)
{
    extern __shared__ float sm[];
    float4* FA = (float4*)sm;                // hh buffer A
    float4* FB = (float4*)(sm + FBUF);       // hh buffer B (s_x in prologue)
    float4* FC = (float4*)(sm + 2 * FBUF);   // cc (h1 in prologue)
    float*  s_in = sm + 3 * FBUF;            // [2][32] current LSTM input

    const int tid  = threadIdx.x;
    const int lane = tid & 31;
    const int w    = tid >> 5;
    const int m0   = blockIdx.x * MROWS;

    // ---------------- Prologue: load X tile (transposed into LL layout) ----
    {
        const int K4 = SD / 4;  // 112
        for (int idx = tid; idx < MROWS * K4; idx += NTHREADS) {
            int r = idx / K4, k4 = idx % K4;
            float4 v = ((const float4*)plh)[(size_t)(m0 + r) * K4 + k4];
            FB[k4 * 32 + r] = v;
        }
    }
    __syncthreads();

    // ---------------- GEMM1: h1 = leaky_relu(X @ W1^T + b1) -> FC ----------
    // warp w owns cols [w*64, w*64+64), 8 chunks of 8 cols
    for (int ch = 0; ch < 8; ch++) {
        const int j0 = w * 64 + ch * 8;
        float acc[8];
        #pragma unroll
        for (int jj = 0; jj < 8; jj++) acc[jj] = b1[j0 + jj];
        const float4* wp = (const float4*)(W1 + (size_t)j0 * SD);  // row = 112 f4
        const float4* xp = FB + lane;
        #pragma unroll 2
        for (int k4 = 0; k4 < SD / 4; k4++) {
            float4 x = xp[k4 * 32];
            #pragma unroll
            for (int jj = 0; jj < 8; jj++) {
                float4 wv = __ldg(wp + jj * (SD / 4) + k4);
                acc[jj] = dot4acc(wv, x, acc[jj]);
            }
        }
        #pragma unroll
        for (int jj = 0; jj < 8; jj += 4) {
            float4 o;
            o.x = lrelu(acc[jj + 0]);
            o.y = lrelu(acc[jj + 1]);
            o.z = lrelu(acc[jj + 2]);
            o.w = lrelu(acc[jj + 3]);
            FC[((j0 + jj) >> 2) * 32 + lane] = o;
        }
    }
    __syncthreads();

    // ---------------- GEMM2: h2 = h1 @ W2^T + b2 -> FA[0:448] --------------
    // warp w owns cols [w*56, w*56+56), 7 chunks of 8 cols
    for (int ch = 0; ch < 7; ch++) {
        const int j0 = w * 56 + ch * 8;
        float acc[8];
        #pragma unroll
        for (int jj = 0; jj < 8; jj++) acc[jj] = b2[j0 + jj];
        const float4* wp = (const float4*)(W2 + (size_t)j0 * HDIM);  // row = 128 f4
        const float4* xp = FC + lane;
        #pragma unroll 2
        for (int k4 = 0; k4 < HDIM / 4; k4++) {
            float4 x = xp[k4 * 32];
            #pragma unroll
            for (int jj = 0; jj < 8; jj++) {
                float4 wv = __ldg(wp + jj * (HDIM / 4) + k4);
                acc[jj] = dot4acc(wv, x, acc[jj]);
            }
        }
        #pragma unroll
        for (int jj = 0; jj < 8; jj += 4) {
            float4 o;
            o.x = acc[jj + 0];
            o.y = acc[jj + 1];
            o.z = acc[jj + 2];
            o.w = acc[jj + 3];
            FA[((j0 + jj) >> 2) * 32 + lane] = o;
        }
    }
    __syncthreads();

    // ---------------- Noise concat into FA[448:512], zero cc, init input ---
    for (int idx = tid; idx < 32 * 16; idx += NTHREADS) {   // 16 q-float4 x 32 rows
        int r = idx & 31, q4 = idx >> 5;
        int n = (m0 + r) & (NPED - 1);
        int gid = n >> 5;                                    // step = N/GROUPS = 32
        float4 v = ((const float4*)zdec)[gid * 16 + q4];
        FA[(112 + q4) * 32 + r] = v;                         // 448>>2 = 112
    }
    for (int idx = tid; idx < FBUF; idx += NTHREADS) ((float*)FC)[idx] = 0.0f;
    if (tid < 64) {
        int r = tid & 31, c = tid >> 5;
        int n = (m0 + r) & (NPED - 1);
        s_in[c * 32 + r] = obs[((size_t)(OBS_LEN - 1) * NPED + n) * NCOORD + c];
    }
    __syncthreads();

    // ---------------- LSTM recurrence: 12 steps ----------------------------
    float4* cur = FA;
    float4* nxt = FB;

    for (int t = 0; t < FUT_LEN; t++) {
        const float xi0 = s_in[lane];
        const float xi1 = s_in[32 + lane];

        // warp w owns hidden cols [w*64, w*64+64), 16 chunks of 4 cells
        for (int ch = 0; ch < 16; ch++) {
            const int j0 = w * 64 + ch * 4;
            float acc[4][4];   // [jj][gate]  gates: 0=i 1=f 2=g 3=o
            #pragma unroll
            for (int g = 0; g < 4; g++) {
                #pragma unroll
                for (int jj = 0; jj < 4; jj++) {
                    int gi = g * HDIM + j0 + jj;
                    float a = bih[gi] + bhh[gi];
                    a = fmaf(Wih[gi * 2 + 0], xi0, a);
                    a = fmaf(Wih[gi * 2 + 1], xi1, a);
                    acc[jj][g] = a;
                }
            }

            const float4* p0 = (const float4*)(Whh + (size_t)(0 * HDIM + j0) * HDIM);
            const float4* p1 = (const float4*)(Whh + (size_t)(1 * HDIM + j0) * HDIM);
            const float4* p2 = (const float4*)(Whh + (size_t)(2 * HDIM + j0) * HDIM);
            const float4* p3 = (const float4*)(Whh + (size_t)(3 * HDIM + j0) * HDIM);
            const float4* xp = cur + lane;

            #pragma unroll 2
            for (int k4 = 0; k4 < HDIM / 4; k4++) {
                float4 x = xp[k4 * 32];
                #pragma unroll
                for (int jj = 0; jj < 4; jj++) {
                    float4 w0 = __ldg(p0 + jj * (HDIM / 4) + k4);
                    acc[jj][0] = dot4acc(w0, x, acc[jj][0]);
                    float4 w1 = __ldg(p1 + jj * (HDIM / 4) + k4);
                    acc[jj][1] = dot4acc(w1, x, acc[jj][1]);
                    float4 w2 = __ldg(p2 + jj * (HDIM / 4) + k4);
                    acc[jj][2] = dot4acc(w2, x, acc[jj][2]);
                    float4 w3 = __ldg(p3 + jj * (HDIM / 4) + k4);
                    acc[jj][3] = dot4acc(w3, x, acc[jj][3]);
                }
            }

            // gating + state update
            const int si = (j0 >> 2) * 32 + lane;
            float4 cold = FC[si];
            float4 cnew, hnew;
            {
                float cn = hsig(acc[0][1]) * cold.x + hsig(acc[0][0]) * htanh(acc[0][2]);
                cnew.x = cn; hnew.x = hsig(acc[0][3]) * htanh(cn);
            }
            {
                float cn = hsig(acc[1][1]) * cold.y + hsig(acc[1][0]) * htanh(acc[1][2]);
                cnew.y = cn; hnew.y = hsig(acc[1][3]) * htanh(cn);
            }
            {
                float cn = hsig(acc[2][1]) * cold.z + hsig(acc[2][0]) * htanh(acc[2][2]);
                cnew.z = cn; hnew.z = hsig(acc[2][3]) * htanh(cn);
            }
            {
                float cn = hsig(acc[3][1]) * cold.w + hsig(acc[3][0]) * htanh(acc[3][2]);
                cnew.w = cn; hnew.w = hsig(acc[3][3]) * htanh(cn);
            }
            FC[si]  = cnew;
            nxt[si] = hnew;
        }
        __syncthreads();

        // out = hh_new @ Wpos^T + bpos ; feeds next input + global output
        if (tid < 64) {
            int r = tid & 31, c = tid >> 5;
            float a = bpos[c];
            const float4* wp = (const float4*)(Wpos + (size_t)c * HDIM);
            const float4* hp = nxt + r;
            #pragma unroll 4
            for (int k4 = 0; k4 < HDIM / 4; k4++) {
                a = dot4acc(__ldg(wp + k4), hp[k4 * 32], a);
            }
            int m  = m0 + r;
            int kk = m >> 11;           // m / NPED
            int n  = m & (NPED - 1);
            out[(((size_t)t * KSAMP + kk) * NPED + n) * NCOORD + c] = a;
            s_in[c * 32 + r] = a;
        }
        __syncthreads();

        float4* tmp = cur; cur = nxt; nxt = tmp;
    }
}

extern "C" void kernel_launch(void* const* d_in, const int* in_sizes, int n_in,
                              void* d_out, int out_size) {
    const float* obs  = (const float*)d_in[0];
    // d_in[1] fut_traj_rel : unused by reference
    // d_in[2] seq_start_end: starts are arange(0,2048,32) -> gid = n>>5
    const float* plh  = (const float*)d_in[3];
    const float* zdec = (const float*)d_in[4];
    const float* W1   = (const float*)d_in[5];
    const float* b1   = (const float*)d_in[6];
    const float* W2   = (const float*)d_in[7];
    const float* b2   = (const float*)d_in[8];
    const float* Wih  = (const float*)d_in[9];
    const float* Whh  = (const float*)d_in[10];
    const float* bih  = (const float*)d_in[11];
    const float* bhh  = (const float*)d_in[12];
    const float* Wpos = (const float*)d_in[13];
    const float* bpos = (const float*)d_in[14];
    float* o = (float*)d_out;

    cudaFuncSetAttribute(predictor_kernel,
                         cudaFuncAttributeMaxDynamicSharedMemorySize, SMEM_BYTES);

    const int nblocks = (KSAMP * NPED) / MROWS;  // 1280
    predictor_kernel<<<nblocks, NTHREADS, SMEM_BYTES>>>(
        obs, plh, zdec, W1, b1, W2, b2, Wih, Whh, bih, bhh, Wpos, bpos, o);
}

// round 5
// speedup vs baseline: 1.0012x; 1.0012x over previous
#include <cuda_runtime.h>
#include <cstddef>

// Problem constants
#define OBS_LEN 8
#define FUT_LEN 12
#define NCOORD  2
#define SD      448   // S_DIM + Z_DIM
#define HDIM    512   // SD + NOISE
#define KSAMP   20
#define NPED    2048
#define MROWS   32    // rows per block
#define NTHREADS 256

#define FBUF 16384                 // 512*32 floats per state buffer
#define SMEM_FLOATS (3*FBUF + 64)  // hhA, hhB, cc, s_in
#define SMEM_BYTES  (SMEM_FLOATS * 4)

__device__ __forceinline__ float hsig(float x) {
    return fminf(fmaxf(x * (1.0f / 6.0f) + 0.5f, 0.0f), 1.0f);
}
__device__ __forceinline__ float htanh(float x) {
    return fminf(fmaxf(x, -1.0f), 1.0f);
}
__device__ __forceinline__ float lrelu(float x) {
    return fmaxf(x, 0.01f * x);
}
__device__ __forceinline__ float dot4acc(float4 w, float4 x, float a) {
    a = fmaf(w.x, x.x, a);
    a = fmaf(w.y, x.y, a);
    a = fmaf(w.z, x.z, a);
    a = fmaf(w.w, x.w, a);
    return a;
}

// State layout LL(j, r): float4 array F[(j>>2)*32 + r], component (j&3).
// - GEMM k-reads:   F[k4*32 + lane]          (LDS.128, 4-phase, conflict-free)
// - per-cell write: F[(j0>>2)*32 + lane]     (chunk j0 aligned to 4)

__global__ void __launch_bounds__(NTHREADS, 1)
predictor_kernel(const float* __restrict__ obs,    // (8,2048,2)
                 const float* __restrict__ plh,    // (20,2048,448)
                 const float* __restrict__ zdec,   // (64,64)
                 const float* __restrict__ W1,     // (512,448)
                 const float* __restrict__ b1,     // (512)
                 const float* __restrict__ W2,     // (448,512)
                 const float* __restrict__ b2,     // (448)
                 const float* __restrict__ Wih,    // (2048,2)
                 const float* __restrict__ Whh,    // (2048,512)
                 const float* __restrict__ bih,    // (2048)
                 const float* __restrict__ bhh,    // (2048)
                 const float* __restrict__ Wpos,   // (2,512)
                 const float* __restrict__ bpos,   // (2)
                 float* __restrict__ out)          // (12,20,2048,2)
{
    extern __shared__ float sm[];
    float4* FA = (float4*)sm;                // hh buffer A
    float4* FB = (float4*)(sm + FBUF);       // hh buffer B (s_x in prologue)
    float4* FC = (float4*)(sm + 2 * FBUF);   // cc (h1 in prologue)
    float*  s_in = sm + 3 * FBUF;            // [2][32] current LSTM input

    const int tid  = threadIdx.x;
    const int lane = tid & 31;
    const int w    = tid >> 5;
    const int m0   = blockIdx.x * MROWS;

    // ---------------- Prologue: load X tile (transposed into LL layout) ----
    {
        const int K4 = SD / 4;  // 112
        for (int idx = tid; idx < MROWS * K4; idx += NTHREADS) {
            int r = idx / K4, k4 = idx % K4;
            float4 v = ((const float4*)plh)[(size_t)(m0 + r) * K4 + k4];
            FB[k4 * 32 + r] = v;
        }
    }
    __syncthreads();

    // ---------------- GEMM1: h1 = leaky_relu(X @ W1^T + b1) -> FC ----------
    // warp w owns cols [w*64, w*64+64), 8 chunks of 8 cols
    for (int ch = 0; ch < 8; ch++) {
        const int j0 = w * 64 + ch * 8;
        float acc[8];
        #pragma unroll
        for (int jj = 0; jj < 8; jj++) acc[jj] = b1[j0 + jj];
        const float4* wp = (const float4*)(W1 + (size_t)j0 * SD);  // row = 112 f4
        const float4* xp = FB + lane;
        #pragma unroll 2
        for (int k4 = 0; k4 < SD / 4; k4++) {
            float4 x = xp[k4 * 32];
            #pragma unroll
            for (int jj = 0; jj < 8; jj++) {
                float4 wv = __ldg(wp + jj * (SD / 4) + k4);
                acc[jj] = dot4acc(wv, x, acc[jj]);
            }
        }
        #pragma unroll
        for (int jj = 0; jj < 8; jj += 4) {
            float4 o;
            o.x = lrelu(acc[jj + 0]);
            o.y = lrelu(acc[jj + 1]);
            o.z = lrelu(acc[jj + 2]);
            o.w = lrelu(acc[jj + 3]);
            FC[((j0 + jj) >> 2) * 32 + lane] = o;
        }
    }
    __syncthreads();

    // ---------------- GEMM2: h2 = h1 @ W2^T + b2 -> FA[0:448] --------------
    // warp w owns cols [w*56, w*56+56), 7 chunks of 8 cols
    for (int ch = 0; ch < 7; ch++) {
        const int j0 = w * 56 + ch * 8;
        float acc[8];
        #pragma unroll
        for (int jj = 0; jj < 8; jj++) acc[jj] = b2[j0 + jj];
        const float4* wp = (const float4*)(W2 + (size_t)j0 * HDIM);  // row = 128 f4
        const float4* xp = FC + lane;
        #pragma unroll 2
        for (int k4 = 0; k4 < HDIM / 4; k4++) {
            float4 x = xp[k4 * 32];
            #pragma unroll
            for (int jj = 0; jj < 8; jj++) {
                float4 wv = __ldg(wp + jj * (HDIM / 4) + k4);
                acc[jj] = dot4acc(wv, x, acc[jj]);
            }
        }
        #pragma unroll
        for (int jj = 0; jj < 8; jj += 4) {
            float4 o;
            o.x = acc[jj + 0];
            o.y = acc[jj + 1];
            o.z = acc[jj + 2];
            o.w = acc[jj + 3];
            FA[((j0 + jj) >> 2) * 32 + lane] = o;
        }
    }
    __syncthreads();

    // ---------------- Noise concat into FA[448:512], zero cc, init input ---
    for (int idx = tid; idx < 32 * 16; idx += NTHREADS) {   // 16 q-float4 x 32 rows
        int r = idx & 31, q4 = idx >> 5;
        int n = (m0 + r) & (NPED - 1);
        int gid = n >> 5;                                    // step = N/GROUPS = 32
        float4 v = ((const float4*)zdec)[gid * 16 + q4];
        FA[(112 + q4) * 32 + r] = v;                         // 448>>2 = 112
    }
    for (int idx = tid; idx < FBUF; idx += NTHREADS) ((float*)FC)[idx] = 0.0f;
    if (tid < 64) {
        int r = tid & 31, c = tid >> 5;
        int n = (m0 + r) & (NPED - 1);
        s_in[c * 32 + r] = obs[((size_t)(OBS_LEN - 1) * NPED + n) * NCOORD + c];
    }
    __syncthreads();

    // ---------------- LSTM recurrence: 12 steps ----------------------------
    float4* cur = FA;
    float4* nxt = FB;

    for (int t = 0; t < FUT_LEN; t++) {
        const float xi0 = s_in[lane];
        const float xi1 = s_in[32 + lane];

        // warp w owns hidden cols [w*64, w*64+64), 16 chunks of 4 cells
        for (int ch = 0; ch < 16; ch++) {
            const int j0 = w * 64 + ch * 4;
            float acc[4][4];   // [jj][gate]  gates: 0=i 1=f 2=g 3=o
            #pragma unroll
            for (int g = 0; g < 4; g++) {
                #pragma unroll
                for (int jj = 0; jj < 4; jj++) {
                    int gi = g * HDIM + j0 + jj;
                    float a = bih[gi] + bhh[gi];
                    a = fmaf(Wih[gi * 2 + 0], xi0, a);
                    a = fmaf(Wih[gi * 2 + 1], xi1, a);
                    acc[jj][g] = a;
                }
            }

            const float4* p0 = (const float4*)(Whh + (size_t)(0 * HDIM + j0) * HDIM);
            const float4* p1 = (const float4*)(Whh + (size_t)(1 * HDIM + j0) * HDIM);
            const float4* p2 = (const float4*)(Whh + (size_t)(2 * HDIM + j0) * HDIM);
            const float4* p3 = (const float4*)(Whh + (size_t)(3 * HDIM + j0) * HDIM);
            const float4* xp = cur + lane;

            #pragma unroll 2
            for (int k4 = 0; k4 < HDIM / 4; k4++) {
                float4 x = xp[k4 * 32];
                #pragma unroll
                for (int jj = 0; jj < 4; jj++) {
                    float4 w0 = __ldg(p0 + jj * (HDIM / 4) + k4);
                    acc[jj][0] = dot4acc(w0, x, acc[jj][0]);
                    float4 w1 = __ldg(p1 + jj * (HDIM / 4) + k4);
                    acc[jj][1] = dot4acc(w1, x, acc[jj][1]);
                    float4 w2 = __ldg(p2 + jj * (HDIM / 4) + k4);
                    acc[jj][2] = dot4acc(w2, x, acc[jj][2]);
                    float4 w3 = __ldg(p3 + jj * (HDIM / 4) + k4);
                    acc[jj][3] = dot4acc(w3, x, acc[jj][3]);
                }
            }

            // gating + state update
            const int si = (j0 >> 2) * 32 + lane;
            float4 cold = FC[si];
            float4 cnew, hnew;
            {
                float cn = hsig(acc[0][1]) * cold.x + hsig(acc[0][0]) * htanh(acc[0][2]);
                cnew.x = cn; hnew.x = hsig(acc[0][3]) * htanh(cn);
            }
            {
                float cn = hsig(acc[1][1]) * cold.y + hsig(acc[1][0]) * htanh(acc[1][2]);
                cnew.y = cn; hnew.y = hsig(acc[1][3]) * htanh(cn);
            }
            {
                float cn = hsig(acc[2][1]) * cold.z + hsig(acc[2][0]) * htanh(acc[2][2]);
                cnew.z = cn; hnew.z = hsig(acc[2][3]) * htanh(cn);
            }
            {
                float cn = hsig(acc[3][1]) * cold.w + hsig(acc[3][0]) * htanh(acc[3][2]);
                cnew.w = cn; hnew.w = hsig(acc[3][3]) * htanh(cn);
            }
            FC[si]  = cnew;
            nxt[si] = hnew;
        }
        __syncthreads();

        // out = hh_new @ Wpos^T + bpos ; feeds next input + global output
        if (tid < 64) {
            int r = tid & 31, c = tid >> 5;
            float a = bpos[c];
            const float4* wp = (const float4*)(Wpos + (size_t)c * HDIM);
            const float4* hp = nxt + r;
            #pragma unroll 4
            for (int k4 = 0; k4 < HDIM / 4; k4++) {
                a = dot4acc(__ldg(wp + k4), hp[k4 * 32], a);
            }
            int m  = m0 + r;
            int kk = m >> 11;           // m / NPED
            int n  = m & (NPED - 1);
            out[(((size_t)t * KSAMP + kk) * NPED + n) * NCOORD + c] = a;
            s_in[c * 32 + r] = a;
        }
        __syncthreads();

        float4* tmp = cur; cur = nxt; nxt = tmp;
    }
}

extern "C" void kernel_launch(void* const* d_in, const int* in_sizes, int n_in,
                              void* d_out, int out_size) {
    const float* obs  = (const float*)d_in[0];
    // d_in[1] fut_traj_rel : unused by reference
    // d_in[2] seq_start_end: starts are arange(0,2048,32) -> gid = n>>5
    const float* plh  = (const float*)d_in[3];
    const float* zdec = (const float*)d_in[4];
    const float* W1   = (const float*)d_in[5];
    const float* b1   = (const float*)d_in[6];
    const float* W2   = (const float*)d_in[7];
    const float* b2   = (const float*)d_in[8];
    const float* Wih  = (const float*)d_in[9];
    const float* Whh  = (const float*)d_in[10];
    const float* bih  = (const float*)d_in[11];
    const float* bhh  = (const float*)d_in[12];
    const float* Wpos = (const float*)d_in[13];
    const float* bpos = (const float*)d_in[14];
    float* o = (float*)d_out;

    cudaFuncSetAttribute(predictor_kernel,
                         cudaFuncAttributeMaxDynamicSharedMemorySize, SMEM_BYTES);

    const int nblocks = (KSAMP * NPED) / MROWS;  // 1280
    predictor_kernel<<<nblocks, NTHREADS, SMEM_BYTES>>>(
        obs, plh, zdec, W1, b1, W2, b2, Wih, Whh, bih, bhh, Wpos, bpos, o);
}